// round 13
// baseline (speedup 1.0000x reference)
#include <cuda_runtime.h>
#include <cuda_bf16.h>

#define N_NODES 100000
#define N_EDGES 1600000
#define NRELS 8
#define HID 128
#define N_TYPES 250
#define NG 64
#define NCLS 49
#define MAXDEG 64
#define PROJ_BLOCKS 225   // 9 col-tiles x 25 row-chunks
#define GATHER_BLOCKS 1184 // 148 SMs x 8 blocks (persistent)

// ---- scratch (device globals; no allocation allowed) ----
__device__ __align__(16) float g_projr[N_TYPES * HID];                 // fp32 root proj (+bias), 128 KB
__device__ __align__(16) __nv_bfloat16 g_projh[N_TYPES * NRELS * HID]; // bf16 rel proj, 512 KB
__device__ int g_cur[N_NODES];                                         // bucket fill
__device__ unsigned short g_csr[(size_t)N_NODES * MAXDEG];             // 12.8 MB keys (t*8+r)
__device__ unsigned char g_type8[N_NODES];                             // 100 KB
__device__ unsigned char g_msk[N_NODES];                               // 100 KB
__device__ int g_list[N_NODES];                                        // packed n|g<<17|t<<23
__device__ int g_ncount = 0;          // always 0 at kernel_launch entry; k_out re-zeroes it
__device__ float g_seg[NG * HID];
__device__ float g_segcnt[NG];

// Fused setup: blocks [0,225) compute proj tables; the rest do the node pass.
__global__ void k_setup(const float* __restrict__ emb,
                        const float* __restrict__ w_rel,
                        const float* __restrict__ w_root,
                        const float* __restrict__ bias,
                        const int* __restrict__ x,
                        const int* __restrict__ nt,
                        const int* __restrict__ batch) {
    __shared__ float semb[10][128];
    const int tid = threadIdx.x;
    if (blockIdx.x < PROJ_BLOCKS) {
        const int bx = blockIdx.x % 9;      // 0..7 = rel r, 8 = root
        const int y0 = (blockIdx.x / 9) * 10;
        for (int idx = tid; idx < 1280; idx += 128) {
            semb[idx >> 7][idx & 127] = emb[(y0 + (idx >> 7)) * 128 + (idx & 127)];
        }
        __syncthreads();
        float acc[10];
#pragma unroll
        for (int t = 0; t < 10; t++) acc[t] = 0.f;
        const float* wp = (bx < 8) ? (w_rel + (size_t)bx * 16384 + tid)
                                   : (w_root + tid);
#pragma unroll 4
        for (int d = 0; d < 128; d++) {
            float wv = wp[(size_t)d * 128];
#pragma unroll
            for (int t = 0; t < 10; t++) acc[t] += semb[t][d] * wv;
        }
        if (bx < 8) {
#pragma unroll
            for (int t = 0; t < 10; t++)
                g_projh[((y0 + t) * NRELS + bx) * HID + tid] = __float2bfloat16_rn(acc[t]);
        } else {
            const float bv = bias[tid];
#pragma unroll
            for (int t = 0; t < 10; t++)
                g_projr[(y0 + t) * HID + tid] = acc[t] + bv;
        }
        return;
    }
    // ---- prep half ----
    const int n = (blockIdx.x - PROJ_BLOCKS) * 128 + tid;
    const int lane = tid & 31;
    if (n < NG * HID) g_seg[n] = 0.f;
    if (n < NG) g_segcnt[n] = 0.f;
    const bool valid = (n < N_NODES);
    int t = 0, m = 1, g = 0;
    if (valid) {
        t = x[n]; m = nt[n]; g = batch[n];
        g_type8[n] = (unsigned char)t;
        g_msk[n] = (m == 0) ? 1 : 0;
        g_cur[n] = 0;
    }
    const bool keep = valid && (m == 0);
    const unsigned full = 0xffffffffu;
    const unsigned ball = __ballot_sync(full, keep);
    const int cnt = __popc(ball);
    int base = 0;
    if (lane == 0 && cnt) base = atomicAdd(&g_ncount, cnt);
    base = __shfl_sync(full, base, 0);
    if (keep) {
        int pos = base + __popc(ball & ((1u << lane) - 1u));
        g_list[pos] = n | (g << 17) | (t << 23);
    }
    const unsigned grp = __match_any_sync(full, keep ? g : -1);
    if (keep && lane == (__ffs(grp) - 1))
        atomicAdd(&g_segcnt[g], (float)__popc(grp));
}

// Bucket-CSR build: 4 edges/thread; type load PREDICATED on the mask so only
// surviving edges pay the random g_type8 wavefront (4.8M -> 4.0M wavefronts).
__global__ void __launch_bounds__(256, 8) k_build(const int* __restrict__ ei,
                                                  const int* __restrict__ et) {
    const int e4 = blockIdx.x * blockDim.x + threadIdx.x;
    if (e4 >= N_EDGES / 4) return;
    const int4 sv = ((const int4*)ei)[e4];
    const int4 dv = ((const int4*)(ei + N_EDGES))[e4];
    const int4 rv = ((const int4*)et)[e4];
    const int ss[4] = {sv.x, sv.y, sv.z, sv.w};
    const int dd[4] = {dv.x, dv.y, dv.z, dv.w};
    const int rr[4] = {rv.x, rv.y, rv.z, rv.w};
    unsigned char mk[4];
#pragma unroll
    for (int j = 0; j < 4; j++) mk[j] = g_msk[dd[j]];
#pragma unroll
    for (int j = 0; j < 4; j++) {
        if (!mk[j]) continue;
        const int ty = g_type8[ss[j]];
        const int slot = atomicAdd(&g_cur[dd[j]], 1);
        if (slot < MAXDEG)
            g_csr[(size_t)dd[j] * MAXDEG + slot] = (unsigned short)(ty * NRELS + rr[j]);
    }
}

// Persistent gather: fixed chip-capacity grid, warp-strided over compacted
// node list. Per node: rel counts via ballots (B-side skipped when deg<=32),
// resolved {w,w,offIdx} staged in smem, unroll-x8 message loop of
// LDS.128 + IMAD.WIDE + LDG.64(bf16) + 4 ALU decode + 2 fma.rn.f32x2.
__global__ void __launch_bounds__(256, 8) k_gather() {
    __shared__ uint4 sbuf[8][MAXDEG];
    const int lane = threadIdx.x & 31;
    const int wslot = threadIdx.x >> 5;
    const int nwarps = GATHER_BLOCKS * 8;
    const int ncnt = g_ncount;
    const unsigned full = 0xffffffffu;

    for (int idx = blockIdx.x * 8 + wslot; idx < ncnt; idx += nwarps) {
        const int packed = g_list[idx];
        const int n = packed & 0x1ffff;
        const int g = (packed >> 17) & 63;
        const int t0 = packed >> 23;

        const float4 rt = ((const float4*)g_projr)[t0 * 32 + lane];
        unsigned long long acc01, acc23;
        asm("mov.b64 %0, {%1,%2};" : "=l"(acc01) : "f"(rt.x), "f"(rt.y));
        asm("mov.b64 %0, {%1,%2};" : "=l"(acc23) : "f"(rt.z), "f"(rt.w));

        const int deg = min(g_cur[n], MAXDEG);
        const unsigned short* row = g_csr + (size_t)n * MAXDEG;
        const int ka = row[lane];
        const int ra = ka & 7;

        const unsigned a0 = __ballot_sync(full, ra & 1);
        const unsigned a1 = __ballot_sync(full, ra & 2);
        const unsigned a2 = __ballot_sync(full, ra & 4);

        if (deg <= 32) {   // warp-uniform; ~99.99% of nodes (deg ~ Poisson(16))
            const unsigned mA = (deg >= 32) ? full : ((1u << deg) - 1u);
            const unsigned sa = ((ra & 1) ? a0 : ~a0) & ((ra & 2) ? a1 : ~a1) & ((ra & 4) ? a2 : ~a2);
            const float wa = 1.0f / fmaxf((float)__popc(sa & mA), 1.0f);
            const unsigned wau = __float_as_uint((lane < deg) ? wa : 0.f);
            sbuf[wslot][lane] = make_uint4(wau, wau, (unsigned)(ka * 32), 0u);
        } else {
            const int kb = row[lane + 32];
            const int rb = kb & 7;
            const int d2 = deg - 32;
            const unsigned mB = (d2 >= 32) ? full : ((1u << d2) - 1u);
            const unsigned b0 = __ballot_sync(full, rb & 1);
            const unsigned b1 = __ballot_sync(full, rb & 2);
            const unsigned b2 = __ballot_sync(full, rb & 4);
            const unsigned sa = ((ra & 1) ? a0 : ~a0) & ((ra & 2) ? a1 : ~a1) & ((ra & 4) ? a2 : ~a2);
            const unsigned sb = ((ra & 1) ? b0 : ~b0) & ((ra & 2) ? b1 : ~b1) & ((ra & 4) ? b2 : ~b2);
            const float wa = 1.0f / fmaxf((float)(__popc(sa) + __popc(sb & mB)), 1.0f);
            const unsigned ua = ((rb & 1) ? a0 : ~a0) & ((rb & 2) ? a1 : ~a1) & ((rb & 4) ? a2 : ~a2);
            const unsigned ub = ((rb & 1) ? b0 : ~b0) & ((rb & 2) ? b1 : ~b1) & ((rb & 4) ? b2 : ~b2);
            const float wb = 1.0f / fmaxf((float)(__popc(ua) + __popc(ub & mB)), 1.0f);
            const unsigned wau = __float_as_uint(wa);
            const unsigned wbu = __float_as_uint((lane + 32 < deg) ? wb : 0.f);
            sbuf[wslot][lane]      = make_uint4(wau, wau, (unsigned)(ka * 32), 0u);
            sbuf[wslot][lane + 32] = make_uint4(wbu, wbu, (unsigned)(kb * 32), 0u);
        }
        __syncwarp();

        const uint2* ph2 = (const uint2*)g_projh + lane;   // lane-fixed 64-bit base
        const int degR = (deg + 7) & ~7;
        for (int i = 0; i < degR; i += 8) {
#pragma unroll
            for (int j = 0; j < 8; j++) {
                const uint4 s = sbuf[wslot][i + j];
                unsigned long long ww;
                asm("mov.b64 %0, {%1,%2};" : "=l"(ww) : "r"(s.x), "r"(s.y));
                const uint2 v = ph2[s.z];                   // IMAD.WIDE + LDG.64
                const unsigned e0 = v.x << 16, e1 = v.x & 0xffff0000u;
                const unsigned e2 = v.y << 16, e3 = v.y & 0xffff0000u;
                unsigned long long v01, v23;
                asm("mov.b64 %0, {%1,%2};" : "=l"(v01) : "r"(e0), "r"(e1));
                asm("mov.b64 %0, {%1,%2};" : "=l"(v23) : "r"(e2), "r"(e3));
                asm("fma.rn.f32x2 %0, %1, %2, %0;" : "+l"(acc01) : "l"(v01), "l"(ww));
                asm("fma.rn.f32x2 %0, %1, %2, %0;" : "+l"(acc23) : "l"(v23), "l"(ww));
            }
        }

        float r0, r1, r2, r3;
        asm("mov.b64 {%0,%1}, %2;" : "=f"(r0), "=f"(r1) : "l"(acc01));
        asm("mov.b64 {%0,%1}, %2;" : "=f"(r2), "=f"(r3) : "l"(acc23));
        r0 = fmaxf(r0, 0.f); r1 = fmaxf(r1, 0.f);
        r2 = fmaxf(r2, 0.f); r3 = fmaxf(r3, 0.f);

        float* dstp = &g_seg[g * HID + lane * 4];
        asm volatile("red.global.add.v4.f32 [%0], {%1,%2,%3,%4};"
                     :: "l"(dstp), "f"(r0), "f"(r1), "f"(r2), "f"(r3)
                     : "memory");
        __syncwarp();   // protect sbuf reuse across iterations
    }
}

// Warp-per-(graph,output): two coalesced 512B float4 loads, dot4 + shfl
// reduce. 3136 warps total. Re-zeroes g_ncount for the next launch.
__global__ void k_out(const float* __restrict__ lw,
                      const float* __restrict__ lb,
                      float* __restrict__ out) {
    const int w = (blockIdx.x * blockDim.x + threadIdx.x) >> 5;
    const int lane = threadIdx.x & 31;
    if (w == 0 && lane == 0) g_ncount = 0;
    if (w >= NG * NCLS) return;
    const int g = w / NCLS;
    const int o = w - g * NCLS;
    const float4 sv = ((const float4*)g_seg)[g * 32 + lane];
    const float4 wv = ((const float4*)lw)[o * 32 + lane];
    float p = sv.x * wv.x + sv.y * wv.y + sv.z * wv.z + sv.w * wv.w;
    const unsigned full = 0xffffffffu;
    p += __shfl_xor_sync(full, p, 16);
    p += __shfl_xor_sync(full, p, 8);
    p += __shfl_xor_sync(full, p, 4);
    p += __shfl_xor_sync(full, p, 2);
    p += __shfl_xor_sync(full, p, 1);
    if (lane == 0) {
        const float inv = 1.0f / fmaxf(g_segcnt[g], 1.0f);
        out[g * NCLS + o] = p * inv + lb[o];
    }
}

extern "C" void kernel_launch(void* const* d_in, const int* in_sizes, int n_in,
                              void* d_out, int out_size) {
    const int o = (n_in >= 12) ? 1 : 0;
    const int* x     = (const int*)d_in[0];
    const int* ei    = (const int*)d_in[1];
    const int* et    = (const int*)d_in[2];
    const int* batch = (const int*)d_in[3];
    const int* nt    = (const int*)d_in[4];
    const float* emb    = (const float*)d_in[5 + o];
    const float* w_root = (const float*)d_in[6 + o];
    const float* w_rel  = (const float*)d_in[7 + o];
    const float* bias   = (const float*)d_in[8 + o];
    const float* lw     = (const float*)d_in[9 + o];
    const float* lb     = (const float*)d_in[10 + o];
    float* out = (float*)d_out;

    const int prep_blocks = (N_NODES + 127) / 128;
    k_setup<<<PROJ_BLOCKS + prep_blocks, 128>>>(emb, w_rel, w_root, bias, x, nt, batch);
    k_build<<<(N_EDGES / 4 + 255) / 256, 256>>>(ei, et);
    k_gather<<<GATHER_BLOCKS, 256>>>();
    k_out<<<(NG * NCLS * 32 + 255) / 256, 256>>>(lw, lb, out);
    (void)in_sizes; (void)out_size;
}

// round 16
// speedup vs baseline: 1.0161x; 1.0161x over previous
#include <cuda_runtime.h>
#include <cuda_bf16.h>

#define N_NODES 100000
#define N_EDGES 1600000
#define NRELS 8
#define HID 128
#define N_TYPES 250
#define NG 64
#define NCLS 49
#define MAXDEG 64
#define PROJ_BLOCKS 225   // 9 col-tiles x 25 row-chunks

// ---- scratch (device globals; no allocation allowed) ----
__device__ __align__(16) float g_projr[N_TYPES * HID];                 // fp32 root proj (+bias)
__device__ __align__(16) __nv_bfloat16 g_projh[N_TYPES * NRELS * HID]; // bf16 rel proj, 512 KB
__device__ int g_cur[N_NODES];
__device__ unsigned short g_csr[(size_t)N_NODES * MAXDEG];
__device__ unsigned char g_type8[N_NODES];
__device__ unsigned char g_msk[N_NODES];
__device__ int g_list[N_NODES];
__device__ int g_ncount = 0;          // 0 at entry; k_out re-zeroes
__device__ float g_seg[NG * HID];
__device__ float g_segcnt[NG];

// Fused setup: blocks [0,225) compute proj tables; the rest do the node pass.
__global__ void k_setup(const float* __restrict__ emb,
                        const float* __restrict__ w_rel,
                        const float* __restrict__ w_root,
                        const float* __restrict__ bias,
                        const int* __restrict__ x,
                        const int* __restrict__ nt,
                        const int* __restrict__ batch) {
    __shared__ float semb[10][128];
    const int tid = threadIdx.x;
    if (blockIdx.x < PROJ_BLOCKS) {
        const int bx = blockIdx.x % 9;      // 0..7 = rel r, 8 = root
        const int y0 = (blockIdx.x / 9) * 10;
        for (int idx = tid; idx < 1280; idx += 128) {
            semb[idx >> 7][idx & 127] = emb[(y0 + (idx >> 7)) * 128 + (idx & 127)];
        }
        __syncthreads();
        float acc[10];
#pragma unroll
        for (int t = 0; t < 10; t++) acc[t] = 0.f;
        const float* wp = (bx < 8) ? (w_rel + (size_t)bx * 16384 + tid)
                                   : (w_root + tid);
#pragma unroll 4
        for (int d = 0; d < 128; d++) {
            float wv = wp[(size_t)d * 128];
#pragma unroll
            for (int t = 0; t < 10; t++) acc[t] += semb[t][d] * wv;
        }
        if (bx < 8) {
#pragma unroll
            for (int t = 0; t < 10; t++)
                g_projh[((y0 + t) * NRELS + bx) * HID + tid] = __float2bfloat16_rn(acc[t]);
        } else {
            const float bv = bias[tid];
#pragma unroll
            for (int t = 0; t < 10; t++)
                g_projr[(y0 + t) * HID + tid] = acc[t] + bv;
        }
        return;
    }
    // ---- prep half ----
    const int n = (blockIdx.x - PROJ_BLOCKS) * 128 + tid;
    const int lane = tid & 31;
    if (n < NG * HID) g_seg[n] = 0.f;
    if (n < NG) g_segcnt[n] = 0.f;
    const bool valid = (n < N_NODES);
    int t = 0, m = 1, g = 0;
    if (valid) {
        t = x[n]; m = nt[n]; g = batch[n];
        g_type8[n] = (unsigned char)t;
        g_msk[n] = (m == 0) ? 1 : 0;
        g_cur[n] = 0;
    }
    const bool keep = valid && (m == 0);
    const unsigned full = 0xffffffffu;
    const unsigned ball = __ballot_sync(full, keep);
    const int cnt = __popc(ball);
    int base = 0;
    if (lane == 0 && cnt) base = atomicAdd(&g_ncount, cnt);
    base = __shfl_sync(full, base, 0);
    if (keep) {
        int pos = base + __popc(ball & ((1u << lane) - 1u));
        g_list[pos] = n | (g << 17) | (t << 23);
    }
    const unsigned grp = __match_any_sync(full, keep ? g : -1);
    if (keep && lane == (__ffs(grp) - 1))
        atomicAdd(&g_segcnt[g], (float)__popc(grp));
}

// Bucket-CSR build: 4 edges/thread; streaming (.cs) loads for the edge
// arrays keep L1 free for the hot random g_msk/g_type8 byte tables.
__global__ void __launch_bounds__(256, 8) k_build(const int* __restrict__ ei,
                                                  const int* __restrict__ et) {
    const int e4 = blockIdx.x * blockDim.x + threadIdx.x;
    if (e4 >= N_EDGES / 4) return;
    const int4 sv = __ldcs((const int4*)ei + e4);
    const int4 dv = __ldcs((const int4*)(ei + N_EDGES) + e4);
    const int4 rv = __ldcs((const int4*)et + e4);
    const int ss[4] = {sv.x, sv.y, sv.z, sv.w};
    const int dd[4] = {dv.x, dv.y, dv.z, dv.w};
    const int rr[4] = {rv.x, rv.y, rv.z, rv.w};
    unsigned char mk[4];
#pragma unroll
    for (int j = 0; j < 4; j++) mk[j] = g_msk[dd[j]];
#pragma unroll
    for (int j = 0; j < 4; j++) {
        if (!mk[j]) continue;
        const int ty = g_type8[ss[j]];
        const int slot = atomicAdd(&g_cur[dd[j]], 1);
        if (slot < MAXDEG)
            g_csr[(size_t)dd[j] * MAXDEG + slot] = (unsigned short)(ty * NRELS + rr[j]);
    }
}

// One warp per unmasked node (non-persistent: measured-best launch shape).
// Rel counts via ballots (B-side skipped when deg<=32); smem stage holds
// {w,w,offIdx}; inner loop per message:
// LDS.128 + IMAD.WIDE + LDG.64(bf16 uint2) + 4 ALU decode + 2 fma.rn.f32x2.
__global__ void __launch_bounds__(256, 8) k_gather() {
    __shared__ uint4 sbuf[8][MAXDEG];
    const int gt = blockIdx.x * blockDim.x + threadIdx.x;
    const int idx = gt >> 5;
    const int lane = gt & 31;
    const int wslot = threadIdx.x >> 5;
    if (idx >= g_ncount) return;
    const int packed = g_list[idx];
    const int n = packed & 0x1ffff;
    const int g = (packed >> 17) & 63;
    const int t0 = packed >> 23;

    const float4 rt = ((const float4*)g_projr)[t0 * 32 + lane];
    unsigned long long acc01, acc23;
    asm("mov.b64 %0, {%1,%2};" : "=l"(acc01) : "f"(rt.x), "f"(rt.y));
    asm("mov.b64 %0, {%1,%2};" : "=l"(acc23) : "f"(rt.z), "f"(rt.w));

    const int deg = min(g_cur[n], MAXDEG);
    const unsigned short* row = g_csr + (size_t)n * MAXDEG;
    const int ka = row[lane];
    const int ra = ka & 7;
    const unsigned full = 0xffffffffu;

    const unsigned a0 = __ballot_sync(full, ra & 1);
    const unsigned a1 = __ballot_sync(full, ra & 2);
    const unsigned a2 = __ballot_sync(full, ra & 4);

    if (deg <= 32) {   // warp-uniform; ~99.99% of nodes (deg ~ Poisson(16))
        const unsigned mA = (deg >= 32) ? full : ((1u << deg) - 1u);
        const unsigned sa = ((ra & 1) ? a0 : ~a0) & ((ra & 2) ? a1 : ~a1) & ((ra & 4) ? a2 : ~a2);
        const float wa = 1.0f / fmaxf((float)__popc(sa & mA), 1.0f);
        const unsigned wau = __float_as_uint((lane < deg) ? wa : 0.f);
        sbuf[wslot][lane] = make_uint4(wau, wau, (unsigned)(ka * 32), 0u);
    } else {
        const int kb = row[lane + 32];
        const int rb = kb & 7;
        const int d2 = deg - 32;
        const unsigned mB = (d2 >= 32) ? full : ((1u << d2) - 1u);
        const unsigned b0 = __ballot_sync(full, rb & 1);
        const unsigned b1 = __ballot_sync(full, rb & 2);
        const unsigned b2 = __ballot_sync(full, rb & 4);
        const unsigned sa = ((ra & 1) ? a0 : ~a0) & ((ra & 2) ? a1 : ~a1) & ((ra & 4) ? a2 : ~a2);
        const unsigned sb = ((ra & 1) ? b0 : ~b0) & ((ra & 2) ? b1 : ~b1) & ((ra & 4) ? b2 : ~b2);
        const float wa = 1.0f / fmaxf((float)(__popc(sa) + __popc(sb & mB)), 1.0f);
        const unsigned ua = ((rb & 1) ? a0 : ~a0) & ((rb & 2) ? a1 : ~a1) & ((rb & 4) ? a2 : ~a2);
        const unsigned ub = ((rb & 1) ? b0 : ~b0) & ((rb & 2) ? b1 : ~b1) & ((rb & 4) ? b2 : ~b2);
        const float wb = 1.0f / fmaxf((float)(__popc(ua) + __popc(ub & mB)), 1.0f);
        const unsigned wau = __float_as_uint(wa);
        const unsigned wbu = __float_as_uint((lane + 32 < deg) ? wb : 0.f);
        sbuf[wslot][lane]      = make_uint4(wau, wau, (unsigned)(ka * 32), 0u);
        sbuf[wslot][lane + 32] = make_uint4(wbu, wbu, (unsigned)(kb * 32), 0u);
    }
    __syncwarp();

    const uint2* ph2 = (const uint2*)g_projh + lane;   // lane-fixed 64-bit base
    const int degR = (deg + 7) & ~7;
    for (int i = 0; i < degR; i += 8) {
#pragma unroll
        for (int j = 0; j < 8; j++) {
            const uint4 s = sbuf[wslot][i + j];
            unsigned long long ww;
            asm("mov.b64 %0, {%1,%2};" : "=l"(ww) : "r"(s.x), "r"(s.y));
            const uint2 v = ph2[s.z];                   // IMAD.WIDE + LDG.64
            const unsigned e0 = v.x << 16, e1 = v.x & 0xffff0000u;
            const unsigned e2 = v.y << 16, e3 = v.y & 0xffff0000u;
            unsigned long long v01, v23;
            asm("mov.b64 %0, {%1,%2};" : "=l"(v01) : "r"(e0), "r"(e1));
            asm("mov.b64 %0, {%1,%2};" : "=l"(v23) : "r"(e2), "r"(e3));
            asm("fma.rn.f32x2 %0, %1, %2, %0;" : "+l"(acc01) : "l"(v01), "l"(ww));
            asm("fma.rn.f32x2 %0, %1, %2, %0;" : "+l"(acc23) : "l"(v23), "l"(ww));
        }
    }

    float r0, r1, r2, r3;
    asm("mov.b64 {%0,%1}, %2;" : "=f"(r0), "=f"(r1) : "l"(acc01));
    asm("mov.b64 {%0,%1}, %2;" : "=f"(r2), "=f"(r3) : "l"(acc23));
    r0 = fmaxf(r0, 0.f); r1 = fmaxf(r1, 0.f);
    r2 = fmaxf(r2, 0.f); r3 = fmaxf(r3, 0.f);

    float* dstp = &g_seg[g * HID + lane * 4];
    asm volatile("red.global.add.v4.f32 [%0], {%1,%2,%3,%4};"
                 :: "l"(dstp), "f"(r0), "f"(r1), "f"(r2), "f"(r3)
                 : "memory");
}

// Warp-per-(graph,output): two coalesced 512B float4 loads, dot4 + shfl
// reduce. 3136 warps total. Re-zeroes g_ncount for the next launch.
__global__ void k_out(const float* __restrict__ lw,
                      const float* __restrict__ lb,
                      float* __restrict__ out) {
    const int w = (blockIdx.x * blockDim.x + threadIdx.x) >> 5;
    const int lane = threadIdx.x & 31;
    if (w == 0 && lane == 0) g_ncount = 0;
    if (w >= NG * NCLS) return;
    const int g = w / NCLS;
    const int o = w - g * NCLS;
    const float4 sv = ((const float4*)g_seg)[g * 32 + lane];
    const float4 wv = ((const float4*)lw)[o * 32 + lane];
    float p = sv.x * wv.x + sv.y * wv.y + sv.z * wv.z + sv.w * wv.w;
    const unsigned full = 0xffffffffu;
    p += __shfl_xor_sync(full, p, 16);
    p += __shfl_xor_sync(full, p, 8);
    p += __shfl_xor_sync(full, p, 4);
    p += __shfl_xor_sync(full, p, 2);
    p += __shfl_xor_sync(full, p, 1);
    if (lane == 0) {
        const float inv = 1.0f / fmaxf(g_segcnt[g], 1.0f);
        out[g * NCLS + o] = p * inv + lb[o];
    }
}

extern "C" void kernel_launch(void* const* d_in, const int* in_sizes, int n_in,
                              void* d_out, int out_size) {
    const int o = (n_in >= 12) ? 1 : 0;
    const int* x     = (const int*)d_in[0];
    const int* ei    = (const int*)d_in[1];
    const int* et    = (const int*)d_in[2];
    const int* batch = (const int*)d_in[3];
    const int* nt    = (const int*)d_in[4];
    const float* emb    = (const float*)d_in[5 + o];
    const float* w_root = (const float*)d_in[6 + o];
    const float* w_rel  = (const float*)d_in[7 + o];
    const float* bias   = (const float*)d_in[8 + o];
    const float* lw     = (const float*)d_in[9 + o];
    const float* lb     = (const float*)d_in[10 + o];
    float* out = (float*)d_out;

    const int prep_blocks = (N_NODES + 127) / 128;
    k_setup<<<PROJ_BLOCKS + prep_blocks, 128>>>(emb, w_rel, w_root, bias, x, nt, batch);
    k_build<<<(N_EDGES / 4 + 255) / 256, 256>>>(ei, et);
    k_gather<<<(N_NODES * 32 + 255) / 256, 256>>>();
    k_out<<<(NG * NCLS * 32 + 255) / 256, 256>>>(lw, lb, out);
    (void)in_sizes; (void)out_size;
}